// round 9
// baseline (speedup 1.0000x reference)
#include <cuda_runtime.h>
#include <cuda_fp16.h>

// CPnAction: action = 32768 - 4 * sum_{d,s} |<z_s, z_{shift_d(s)}>|^2 per batch.
// B=1024, 64x64 lattice (S=4096), 6 angles -> z in C^4 (zi[3]=0).
// Two CTAs per batch, each owns 32 rows (2048 sites) + recomputes the next
// chunk's first row as a 64-site halo at local slots [2048,2112).
// Computed shifts (fixed roll(-1) pattern):
//   row+1 neighbor of local l is simply l+64 (halo covers the wrap);
//   col+1 neighbor is (l & ~63) | ((l+1) & 63).
// z packed per site as uint4 of half2: (zr01, zr23, zi01, (zi2,0)) = 16 B
// -> smem 33,792 B. Dots in half2, fp32 accumulation.

#define LROW    64
#define NSITES  4096
#define CHUNK   2048                 // own sites per CTA (32 rows)
#define LOC     (CHUNK + LROW)       // + halo row = 2112
#define NTHR    512
#define SPT     (CHUNK / NTHR)       // 4

__device__ float g_partial[2048];

__device__ __forceinline__ unsigned pack_h2(float a, float b) {
    __half2 h = __floats2half2_rn(a, b);
    return *reinterpret_cast<unsigned*>(&h);
}
__device__ __forceinline__ __half2 u2h(unsigned u) {
    return *reinterpret_cast<__half2*>(&u);
}

__device__ __forceinline__ uint4 compute_z(const float* __restrict__ p)
{
    float2 v0 = *(const float2*)(p);
    float2 v1 = *(const float2*)(p + 2);
    float2 v2 = *(const float2*)(p + 4);
    float ph[6] = {v0.x, v0.y, v1.x, v1.y, v2.x, v2.y};

    float x[7];
    float scum = 1.0f;
    #pragma unroll
    for (int k = 0; k < 6; k++) {
        float s0 = __sinf(ph[k]);
        float c0 = __cosf(ph[k]);
        float sn, cs;
        if (k < 5) { sn = fabsf(s0); cs = (s0 < 0.0f) ? -c0 : c0; }
        else       { sn = s0;        cs = c0; }
        x[k] = cs * scum;
        scum *= sn;
    }
    x[6] = scum;
    return make_uint4(pack_h2(x[0], x[1]), pack_h2(x[2], x[3]),
                      pack_h2(x[4], x[5]), pack_h2(x[6], 0.0f));
}

template<int MINB>
__global__ __launch_bounds__(NTHR, MINB)
void cpn_action_kernel(const float* __restrict__ phi)
{
    extern __shared__ uint4 sZ[];   // [2112]

    const int cta   = blockIdx.x;
    const int b     = cta >> 1;
    const int chunk = cta & 1;
    const int base  = chunk * CHUNK;                       // first own site
    const int hbase = ((base + CHUNK) & (NSITES - 1));     // halo row start
    const int t     = threadIdx.x;

    const float* __restrict__ phb = phi + (size_t)b * NSITES * 6;

    // ---- Pass 1: angles -> z (own 2048 + 64 halo) ----
    #pragma unroll
    for (int i = 0; i < SPT; i++) {
        const int l = t + i * NTHR;
        sZ[l] = compute_z(phb + (base + l) * 6);
    }
    if (t < LROW)
        sZ[CHUNK + t] = compute_z(phb + (hbase + t) * 6);
    __syncthreads();

    // ---- Pass 2: neighbors, accumulate |dot|^2 ----
    float acc = 0.0f;
    #pragma unroll
    for (int i = 0; i < SPT; i++) {
        const int l = t + i * NTHR;
        const uint4 zu = sZ[l];
        const __half2 zr01 = u2h(zu.x), zr23 = u2h(zu.y);
        const __half2 zi01 = u2h(zu.z), zi2p = u2h(zu.w);

        const int j0 = l + LROW;                        // row+1 (halo at end)
        const int j1 = (l & ~63) | ((l + 1) & 63);      // col+1 (wraps in-row)

        #pragma unroll
        for (int d = 0; d < 2; d++) {
            const uint4 au = sZ[d ? j1 : j0];
            const __half2 ar01 = u2h(au.x), ar23 = u2h(au.y);
            const __half2 ai01 = u2h(au.z), ai2p = u2h(au.w);

            __half2 re = __hmul2(zr01, ar01);
            re = __hfma2(zr23, ar23, re);
            __half2 im = __hmul2(zi01, ai01);
            im = __hfma2(zi2p, ai2p, im);
            __half2 dre2 = __hsub2(re, im);
            __half2 dim2 = __hmul2(zr01, ai01);
            dim2 = __hfma2(zr23, ai2p, dim2);
            dim2 = __hfma2(zi01, ar01, dim2);
            dim2 = __hfma2(zi2p, ar23, dim2);

            float dre = __low2float(dre2) + __high2float(dre2);
            float dim = __low2float(dim2) + __high2float(dim2);
            acc = fmaf(dre, dre, acc);
            acc = fmaf(dim, dim, acc);
        }
    }

    // ---- Block reduction -> partial ----
    __shared__ float warpsum[NTHR / 32];
    #pragma unroll
    for (int off = 16; off > 0; off >>= 1)
        acc += __shfl_down_sync(0xffffffffu, acc, off);
    if ((t & 31) == 0) warpsum[t >> 5] = acc;
    __syncthreads();
    if (t < NTHR / 32) {
        acc = warpsum[t];
        #pragma unroll
        for (int off = NTHR / 64; off > 0; off >>= 1)
            acc += __shfl_down_sync(0xffffu, acc, off, NTHR / 32);
        if (t == 0) g_partial[cta] = acc;
    }
}

__global__ void cpn_reduce_kernel(float* __restrict__ out, int B)
{
    const int b = blockIdx.x * blockDim.x + threadIdx.x;
    if (b < B)
        out[b] = 32768.0f - 4.0f * (g_partial[2 * b] + g_partial[2 * b + 1]);
}

extern "C" void kernel_launch(void* const* d_in, const int* in_sizes, int n_in,
                              void* d_out, int out_size)
{
    const float* phi = (const float*)d_in[0];
    float*       out = (float*)d_out;

    const int B = in_sizes[0] / (NSITES * 6);            // 1024
    const int smem_bytes = LOC * (int)sizeof(uint4);     // 33,792 B

    // Pick the 4-CTA/SM build unless the register cap made it spill.
    cudaFuncAttributes a4;
    cudaFuncGetAttributes(&a4, cpn_action_kernel<4>);
    const bool use4 = (a4.localSizeBytes == 0);

    if (use4) {
        cudaFuncSetAttribute(cpn_action_kernel<4>,
                             cudaFuncAttributeMaxDynamicSharedMemorySize, smem_bytes);
        cpn_action_kernel<4><<<2 * B, NTHR, smem_bytes>>>(phi);
    } else {
        cudaFuncSetAttribute(cpn_action_kernel<3>,
                             cudaFuncAttributeMaxDynamicSharedMemorySize, smem_bytes);
        cpn_action_kernel<3><<<2 * B, NTHR, smem_bytes>>>(phi);
    }
    cpn_reduce_kernel<<<(B + 255) / 256, 256>>>(out, B);
}